// round 16
// baseline (speedup 1.0000x reference)
#include <cuda_runtime.h>
#include <math.h>

#define N_ENTITY 64368
#define N_REL 40
#define DIM 128
#define N_BASES 8
#define N_EDGES 500000
#define BATCH 64
#define SEED_LEN 32

#define SCAN_BLK 1024
#define SCAN_NBLK 63            // 63*1024 = 64512 >= 64368
#define HIST_PAD (SCAN_NBLK * SCAN_BLK)

// ------------------------- device scratch (no allocs) ----------------------
// Zero-on-entry invariants, restored within the pipeline each call:
//   g_hist   : zeroed by scan (after reading)
//   g_total  : zeroed by hist (before scan runs)
//   g_deg    : zeroed by scan (before scatter accumulates)
//   g_agg    : zeroed by scatter (before agg accumulates)
//   g_cursor : zeroed by agg (after scatter used it)
__device__ float g_agg[(size_t)N_ENTITY * DIM];
__device__ float g_deg[N_ENTITY];
__device__ float g_u[BATCH * DIM];
__device__ int   g_hist[HIST_PAD];
__device__ int   g_cnt[HIST_PAD];      // persisted per-src count
__device__ int   g_start[HIST_PAD];    // group start
__device__ int   g_cursor[N_ENTITY];
__device__ int   g_total;
__device__ int   g_pack[N_EDGES];      // dst | (type<<20), grouped by src

// ---------------------------------------------------------------------------
// 1) histogram of src only (+ zero g_total for scan)
// ---------------------------------------------------------------------------
__global__ void hist_kernel(const int* __restrict__ src) {
    int e = blockIdx.x * blockDim.x + threadIdx.x;
    if (e == 0) g_total = 0;
    if (e >= N_EDGES) return;
    atomicAdd(&g_hist[src[e]], 1);
}

// ---------------------------------------------------------------------------
// 2) offset allocation: block scan + atomic block base. Persists count into
//    g_cnt, zeroes g_hist and g_deg.
// ---------------------------------------------------------------------------
__global__ void scan_kernel() {
    __shared__ int wsum[32];
    __shared__ int base_s;
    int t = threadIdx.x;
    int lane = t & 31, warp = t >> 5;
    int i = blockIdx.x * SCAN_BLK + t;
    int v = g_hist[i];
    g_hist[i] = 0;                       // restore invariant
    g_cnt[i] = v;
    if (i < N_ENTITY) g_deg[i] = 0.f;    // prepare for scatter's deg atomics

    int x = v;
#pragma unroll
    for (int o = 1; o < 32; o <<= 1) {
        int y = __shfl_up_sync(0xffffffffu, x, o);
        if (lane >= o) x += y;
    }
    if (lane == 31) wsum[warp] = x;
    __syncthreads();
    if (warp == 0) {
        int s = wsum[lane];
#pragma unroll
        for (int o = 1; o < 32; o <<= 1) {
            int y = __shfl_up_sync(0xffffffffu, s, o);
            if (lane >= o) s += y;
        }
        wsum[lane] = s;
    }
    __syncthreads();
    int incl = x + (warp ? wsum[warp - 1] : 0);
    if (t == SCAN_BLK - 1) base_s = atomicAdd(&g_total, incl);
    __syncthreads();
    g_start[i] = base_s + incl - v;
}

// ---------------------------------------------------------------------------
// 3) scatter edges grouped by src + deg accumulation + zero g_agg.
// ---------------------------------------------------------------------------
__global__ void scatter_kernel(const int* __restrict__ src,
                               const int* __restrict__ dst,
                               const int* __restrict__ typ) {
    int e = blockIdx.x * blockDim.x + threadIdx.x;
    int nthreads = gridDim.x * blockDim.x;

    size_t total4 = ((size_t)N_ENTITY * DIM) / 4;
    for (size_t i = e; i < total4; i += nthreads)
        ((float4*)g_agg)[i] = make_float4(0.f, 0.f, 0.f, 0.f);

    if (e >= N_EDGES) return;
    int s = src[e];
    int d = dst[e];
    int pos = g_start[s] + atomicAdd(&g_cursor[s], 1);
    g_pack[pos] = d | (typ[e] << 20);
    atomicAdd(&g_deg[d], 1.0f);
}

// ---------------------------------------------------------------------------
// 4) grouped aggregation (launch #4 -> ncu control). R6/R11 config: one warp
//    per src, flat launch, FFMA2 packed math, v4 RED. Also zeroes g_cursor.
// ---------------------------------------------------------------------------
#define FMA2(acc, c, v) \
    asm("fma.rn.f32x2 %0, %1, %2, %0;" : "+l"(acc) : "l"(c), "l"(v))

__global__ void __launch_bounds__(256)
agg_kernel(const float* __restrict__ basis, const float* __restrict__ att) {
    __shared__ __align__(16) unsigned long long att_dup[N_REL * N_BASES];
    int tid = threadIdx.x;
    for (int i = tid; i < N_REL * N_BASES; i += blockDim.x) {
        unsigned int ci = __float_as_uint(att[i]);
        att_dup[i] = ((unsigned long long)ci << 32) | (unsigned long long)ci;
    }
    __syncthreads();

    int w = (int)((blockIdx.x * blockDim.x + tid) >> 5);
    int lane = tid & 31;
    if (w >= N_ENTITY) return;
    int cnt = g_cnt[w];
    if (lane == 0) g_cursor[w] = 0;     // restore invariant
    if (cnt == 0) return;
    int start = g_start[w];

    unsigned long long r0[N_BASES], r1[N_BASES];
#pragma unroll
    for (int b = 0; b < N_BASES; b++) {
        ulonglong2 v = __ldg(
            (const ulonglong2*)(basis + ((size_t)b * N_ENTITY + (size_t)w) * DIM) + lane);
        r0[b] = v.x;
        r1[b] = v.y;
    }

    float* base_out = g_agg + (size_t)lane * 4;

    for (int i0 = 0; i0 < cnt; i0 += 32) {
        int n = min(32, cnt - i0);
        int pk = 0;
        if (lane < n) pk = g_pack[start + i0 + lane];
        for (int i = 0; i < n; i++) {
            int p = __shfl_sync(0xffffffffu, pk, i);
            int d = p & 0xFFFFF;
            int t = p >> 20;
            const ulonglong2* ad = (const ulonglong2*)(att_dup + t * N_BASES);
            ulonglong2 q0 = ad[0];
            ulonglong2 q1 = ad[1];
            ulonglong2 q2 = ad[2];
            ulonglong2 q3 = ad[3];

            unsigned long long acc0 = 0ull, acc1 = 0ull;
            FMA2(acc0, q0.x, r0[0]); FMA2(acc1, q0.x, r1[0]);
            FMA2(acc0, q0.y, r0[1]); FMA2(acc1, q0.y, r1[1]);
            FMA2(acc0, q1.x, r0[2]); FMA2(acc1, q1.x, r1[2]);
            FMA2(acc0, q1.y, r0[3]); FMA2(acc1, q1.y, r1[3]);
            FMA2(acc0, q2.x, r0[4]); FMA2(acc1, q2.x, r1[4]);
            FMA2(acc0, q2.y, r0[5]); FMA2(acc1, q2.y, r1[5]);
            FMA2(acc0, q3.x, r0[6]); FMA2(acc1, q3.x, r1[6]);
            FMA2(acc0, q3.y, r0[7]); FMA2(acc1, q3.y, r1[7]);

            float a0 = __uint_as_float((unsigned int)acc0);
            float a1 = __uint_as_float((unsigned int)(acc0 >> 32));
            float a2 = __uint_as_float((unsigned int)acc1);
            float a3 = __uint_as_float((unsigned int)(acc1 >> 32));

            float* outp = base_out + (size_t)d * DIM;
            asm volatile("red.global.add.v4.f32 [%0], {%1, %2, %3, %4};"
                         :: "l"(outp), "f"(a0), "f"(a1), "f"(a2), "f"(a3)
                         : "memory");
        }
    }
}

// ---------------------------------------------------------------------------
// 5) finalize: g_agg <- g_agg * invdeg + root + rbias (in place, once).
//    Downstream consumers (attn, scores) then read finished nodes directly.
// ---------------------------------------------------------------------------
__global__ void finalize_kernel(const float* __restrict__ root,
                                const float* __restrict__ rbias) {
    size_t i = (size_t)blockIdx.x * blockDim.x + threadIdx.x;  // float4 index
    size_t total4 = ((size_t)N_ENTITY * DIM) / 4;
    if (i >= total4) return;
    int node = (int)(i >> 5);          // DIM/4 = 32 float4 per node
    int d4 = (int)(i & 31);
    float invd = 1.0f / fmaxf(g_deg[node], 1.0f);
    float4 a = ((float4*)g_agg)[i];
    float4 rt = __ldg((const float4*)root + i);
    float4 bb = __ldg((const float4*)rbias + d4);
    a.x = a.x * invd + rt.x + bb.x;
    a.y = a.y * invd + rt.y + bb.y;
    a.z = a.z * invd + rt.z + bb.z;
    a.w = a.w * invd + rt.w + bb.w;
    ((float4*)g_agg)[i] = a;
}

// ---------------------------------------------------------------------------
// 6) attention pooling (nodes already finalized -> plain gather)
// ---------------------------------------------------------------------------
__global__ void attn_kernel(const int* __restrict__ seed_ids,
                            const float* __restrict__ A,
                            const float* __restrict__ bvec) {
    __shared__ float H[SEED_LEN][DIM + 1];
    __shared__ float e_s[SEED_LEN];
    __shared__ float attnw[SEED_LEN];

    int b = blockIdx.x;
    int tid = threadIdx.x;
    int lane = tid & 31, warp = tid >> 5;

    for (int r = 0; r < SEED_LEN * DIM / 256; r++) {
        int idx = r * 256 + tid;
        int s = idx >> 7, d = idx & 127;
        int node = seed_ids[b * SEED_LEN + s];
        H[s][d] = g_agg[(size_t)node * DIM + d];
    }
    __syncthreads();

    float4 acc[4];
#pragma unroll
    for (int ss = 0; ss < 4; ss++) acc[ss] = make_float4(0.f, 0.f, 0.f, 0.f);
    int s0 = warp * 4;
#pragma unroll 4
    for (int k = 0; k < DIM; k++) {
        float4 a4 = __ldg((const float4*)(A + (size_t)k * DIM) + lane);
        float h0 = H[s0 + 0][k];
        float h1 = H[s0 + 1][k];
        float h2 = H[s0 + 2][k];
        float h3 = H[s0 + 3][k];
        acc[0].x = fmaf(h0, a4.x, acc[0].x); acc[0].y = fmaf(h0, a4.y, acc[0].y);
        acc[0].z = fmaf(h0, a4.z, acc[0].z); acc[0].w = fmaf(h0, a4.w, acc[0].w);
        acc[1].x = fmaf(h1, a4.x, acc[1].x); acc[1].y = fmaf(h1, a4.y, acc[1].y);
        acc[1].z = fmaf(h1, a4.z, acc[1].z); acc[1].w = fmaf(h1, a4.w, acc[1].w);
        acc[2].x = fmaf(h2, a4.x, acc[2].x); acc[2].y = fmaf(h2, a4.y, acc[2].y);
        acc[2].z = fmaf(h2, a4.z, acc[2].z); acc[2].w = fmaf(h2, a4.w, acc[2].w);
        acc[3].x = fmaf(h3, a4.x, acc[3].x); acc[3].y = fmaf(h3, a4.y, acc[3].y);
        acc[3].z = fmaf(h3, a4.z, acc[3].z); acc[3].w = fmaf(h3, a4.w, acc[3].w);
    }

    float4 b4 = __ldg((const float4*)bvec + lane);
#pragma unroll
    for (int ss = 0; ss < 4; ss++) {
        float v = tanhf(acc[ss].x) * b4.x + tanhf(acc[ss].y) * b4.y +
                  tanhf(acc[ss].z) * b4.z + tanhf(acc[ss].w) * b4.w;
#pragma unroll
        for (int o = 16; o > 0; o >>= 1) v += __shfl_xor_sync(0xffffffffu, v, o);
        if (lane == 0) e_s[s0 + ss] = v;
    }
    __syncthreads();

    if (warp == 0) {
        float ev = e_s[lane];
        float m = ev;
#pragma unroll
        for (int o = 16; o > 0; o >>= 1)
            m = fmaxf(m, __shfl_xor_sync(0xffffffffu, m, o));
        float ex = expf(ev - m);
        float ss2 = ex;
#pragma unroll
        for (int o = 16; o > 0; o >>= 1) ss2 += __shfl_xor_sync(0xffffffffu, ss2, o);
        attnw[lane] = ex / ss2;
    }
    __syncthreads();

    if (tid < DIM) {
        float u = 0.f;
#pragma unroll
        for (int s = 0; s < SEED_LEN; s++) u = fmaf(attnw[s], H[s][tid], u);
        g_u[b * DIM + tid] = u;
    }
}

// ---------------------------------------------------------------------------
// 7) scores: loader reads ONLY finalized g_agg (+ small g_u). Conflict-free
//    compute mapping (ti+16*i / tj+16*j) from R15.
// ---------------------------------------------------------------------------
#define ETILE 64
#define KCH 64
__global__ void scores_kernel(const float* __restrict__ out_bias,
                              float* __restrict__ out) {
    __shared__ float nS[ETILE][KCH + 1];
    __shared__ float uS[BATCH][KCH + 1];
    int e0 = blockIdx.x * ETILE;
    int tid = threadIdx.x;
    int ti = tid & 15;   // entities ti, ti+16, ti+32, ti+48
    int tj = tid >> 4;   // batches  tj, tj+16, tj+32, tj+48

    float acc[4][4];
#pragma unroll
    for (int i = 0; i < 4; i++)
#pragma unroll
        for (int j = 0; j < 4; j++) acc[i][j] = 0.f;

    for (int kc = 0; kc < DIM; kc += KCH) {
        __syncthreads();
        for (int q = tid; q < ETILE * (KCH / 4); q += 256) {
            int r = q >> 4;
            int c4 = (q & 15) * 4;
            int e = e0 + r;
            float4 nv = make_float4(0.f, 0.f, 0.f, 0.f);
            if (e < N_ENTITY)
                nv = *(const float4*)(g_agg + (size_t)e * DIM + kc + c4);
            nS[r][c4 + 0] = nv.x; nS[r][c4 + 1] = nv.y;
            nS[r][c4 + 2] = nv.z; nS[r][c4 + 3] = nv.w;
            float4 uv = *(const float4*)(g_u + r * DIM + kc + c4);
            uS[r][c4 + 0] = uv.x; uS[r][c4 + 1] = uv.y;
            uS[r][c4 + 2] = uv.z; uS[r][c4 + 3] = uv.w;
        }
        __syncthreads();
#pragma unroll 8
        for (int k = 0; k < KCH; k++) {
            float nf[4], uf[4];
#pragma unroll
            for (int i = 0; i < 4; i++) nf[i] = nS[ti + 16 * i][k];
#pragma unroll
            for (int j = 0; j < 4; j++) uf[j] = uS[tj + 16 * j][k];
#pragma unroll
            for (int i = 0; i < 4; i++)
#pragma unroll
                for (int j = 0; j < 4; j++)
                    acc[i][j] = fmaf(nf[i], uf[j], acc[i][j]);
        }
    }

#pragma unroll
    for (int i = 0; i < 4; i++) {
        int e = e0 + ti + 16 * i;
        if (e >= N_ENTITY) continue;
        float ob = out_bias[e];
#pragma unroll
        for (int j = 0; j < 4; j++) {
            int bb = tj + 16 * j;
            out[(size_t)bb * N_ENTITY + e] = acc[i][j] + ob;
        }
    }
}

// ---------------------------------------------------------------------------
extern "C" void kernel_launch(void* const* d_in, const int* in_sizes, int n_in,
                              void* d_out, int out_size) {
    const int*   seed_ids = (const int*)d_in[0];
    const int*   edge_src = (const int*)d_in[1];
    const int*   edge_dst = (const int*)d_in[2];
    const int*   edge_typ = (const int*)d_in[3];
    const float* basis    = (const float*)d_in[4];
    const float* att      = (const float*)d_in[5];
    const float* root     = (const float*)d_in[6];
    const float* rbias    = (const float*)d_in[7];
    const float* attn_a   = (const float*)d_in[8];
    const float* attn_b   = (const float*)d_in[9];
    const float* out_bias = (const float*)d_in[10];
    float* out = (float*)d_out;

    hist_kernel<<<(N_EDGES + 255) / 256, 256>>>(edge_src);                        // 1
    scan_kernel<<<SCAN_NBLK, SCAN_BLK>>>();                                       // 2
    scatter_kernel<<<(N_EDGES + 255) / 256, 256>>>(edge_src, edge_dst, edge_typ); // 3
    agg_kernel<<<(N_ENTITY * 32 + 255) / 256, 256>>>(basis, att);                 // 4 (ncu)
    {
        size_t total4 = ((size_t)N_ENTITY * DIM) / 4;
        finalize_kernel<<<(int)((total4 + 255) / 256), 256>>>(root, rbias);       // 5
    }
    attn_kernel<<<BATCH, 256>>>(seed_ids, attn_a, attn_b);                        // 6
    scores_kernel<<<(N_ENTITY + ETILE - 1) / ETILE, 256>>>(out_bias, out);        // 7
}

// round 17
// speedup vs baseline: 1.0367x; 1.0367x over previous
#include <cuda_runtime.h>
#include <math.h>

#define N_ENTITY 64368
#define N_REL 40
#define DIM 128
#define N_BASES 8
#define N_EDGES 500000
#define BATCH 64
#define SEED_LEN 32

#define SCAN_BLK 1024
#define SCAN_NBLK 63            // 63*1024 = 64512 >= 64368
#define HIST_PAD (SCAN_NBLK * SCAN_BLK)

// ------------------------- device scratch (no allocs) ----------------------
// Zero-on-entry invariants, restored within the pipeline each call:
//   g_hist   : zeroed by scan (after reading)
//   g_total  : zeroed by hist (before scan runs)
//   g_deg    : zeroed by scan (before scatter accumulates)
//   g_agg    : zeroed by scatter (before agg accumulates)
//   g_cursor : zeroed by agg (after scatter used it)
__device__ float g_agg[(size_t)N_ENTITY * DIM];
__device__ float g_deg[N_ENTITY];
__device__ float g_u[BATCH * DIM];
__device__ int   g_hist[HIST_PAD];
__device__ int   g_cnt[HIST_PAD];      // persisted per-src count
__device__ int   g_start[HIST_PAD];    // group start
__device__ int   g_cursor[N_ENTITY];
__device__ int   g_total;
__device__ int   g_pack[N_EDGES];      // dst | (type<<20), grouped by src

// ---------------------------------------------------------------------------
// 1) histogram of src only (+ zero g_total for scan)
// ---------------------------------------------------------------------------
__global__ void hist_kernel(const int* __restrict__ src) {
    int e = blockIdx.x * blockDim.x + threadIdx.x;
    if (e == 0) g_total = 0;
    if (e >= N_EDGES) return;
    atomicAdd(&g_hist[src[e]], 1);
}

// ---------------------------------------------------------------------------
// 2) offset allocation: block scan + atomic block base. Persists count into
//    g_cnt, zeroes g_hist and g_deg.
// ---------------------------------------------------------------------------
__global__ void scan_kernel() {
    __shared__ int wsum[32];
    __shared__ int base_s;
    int t = threadIdx.x;
    int lane = t & 31, warp = t >> 5;
    int i = blockIdx.x * SCAN_BLK + t;
    int v = g_hist[i];
    g_hist[i] = 0;                       // restore invariant
    g_cnt[i] = v;
    if (i < N_ENTITY) g_deg[i] = 0.f;    // prepare for scatter's deg atomics

    int x = v;
#pragma unroll
    for (int o = 1; o < 32; o <<= 1) {
        int y = __shfl_up_sync(0xffffffffu, x, o);
        if (lane >= o) x += y;
    }
    if (lane == 31) wsum[warp] = x;
    __syncthreads();
    if (warp == 0) {
        int s = wsum[lane];
#pragma unroll
        for (int o = 1; o < 32; o <<= 1) {
            int y = __shfl_up_sync(0xffffffffu, s, o);
            if (lane >= o) s += y;
        }
        wsum[lane] = s;
    }
    __syncthreads();
    int incl = x + (warp ? wsum[warp - 1] : 0);
    if (t == SCAN_BLK - 1) base_s = atomicAdd(&g_total, incl);
    __syncthreads();
    g_start[i] = base_s + incl - v;
}

// ---------------------------------------------------------------------------
// 3) scatter edges grouped by src + deg accumulation + zero g_agg.
// ---------------------------------------------------------------------------
__global__ void scatter_kernel(const int* __restrict__ src,
                               const int* __restrict__ dst,
                               const int* __restrict__ typ) {
    int e = blockIdx.x * blockDim.x + threadIdx.x;
    int nthreads = gridDim.x * blockDim.x;

    size_t total4 = ((size_t)N_ENTITY * DIM) / 4;
    for (size_t i = e; i < total4; i += nthreads)
        ((float4*)g_agg)[i] = make_float4(0.f, 0.f, 0.f, 0.f);

    if (e >= N_EDGES) return;
    int s = src[e];
    int d = dst[e];
    int pos = g_start[s] + atomicAdd(&g_cursor[s], 1);
    g_pack[pos] = d | (typ[e] << 20);
    atomicAdd(&g_deg[d], 1.0f);
}

// ---------------------------------------------------------------------------
// 4) grouped aggregation (launch #4 -> ncu control). R6/R11 config: one warp
//    per src, flat launch, FFMA2 packed math, v4 RED. Also zeroes g_cursor.
// ---------------------------------------------------------------------------
#define FMA2(acc, c, v) \
    asm("fma.rn.f32x2 %0, %1, %2, %0;" : "+l"(acc) : "l"(c), "l"(v))

__global__ void __launch_bounds__(256)
agg_kernel(const float* __restrict__ basis, const float* __restrict__ att) {
    __shared__ __align__(16) unsigned long long att_dup[N_REL * N_BASES];
    int tid = threadIdx.x;
    for (int i = tid; i < N_REL * N_BASES; i += blockDim.x) {
        unsigned int ci = __float_as_uint(att[i]);
        att_dup[i] = ((unsigned long long)ci << 32) | (unsigned long long)ci;
    }
    __syncthreads();

    int w = (int)((blockIdx.x * blockDim.x + tid) >> 5);
    int lane = tid & 31;
    if (w >= N_ENTITY) return;
    int cnt = g_cnt[w];
    if (lane == 0) g_cursor[w] = 0;     // restore invariant
    if (cnt == 0) return;
    int start = g_start[w];

    unsigned long long r0[N_BASES], r1[N_BASES];
#pragma unroll
    for (int b = 0; b < N_BASES; b++) {
        ulonglong2 v = __ldg(
            (const ulonglong2*)(basis + ((size_t)b * N_ENTITY + (size_t)w) * DIM) + lane);
        r0[b] = v.x;
        r1[b] = v.y;
    }

    float* base_out = g_agg + (size_t)lane * 4;

    for (int i0 = 0; i0 < cnt; i0 += 32) {
        int n = min(32, cnt - i0);
        int pk = 0;
        if (lane < n) pk = g_pack[start + i0 + lane];
        for (int i = 0; i < n; i++) {
            int p = __shfl_sync(0xffffffffu, pk, i);
            int d = p & 0xFFFFF;
            int t = p >> 20;
            const ulonglong2* ad = (const ulonglong2*)(att_dup + t * N_BASES);
            ulonglong2 q0 = ad[0];
            ulonglong2 q1 = ad[1];
            ulonglong2 q2 = ad[2];
            ulonglong2 q3 = ad[3];

            unsigned long long acc0 = 0ull, acc1 = 0ull;
            FMA2(acc0, q0.x, r0[0]); FMA2(acc1, q0.x, r1[0]);
            FMA2(acc0, q0.y, r0[1]); FMA2(acc1, q0.y, r1[1]);
            FMA2(acc0, q1.x, r0[2]); FMA2(acc1, q1.x, r1[2]);
            FMA2(acc0, q1.y, r0[3]); FMA2(acc1, q1.y, r1[3]);
            FMA2(acc0, q2.x, r0[4]); FMA2(acc1, q2.x, r1[4]);
            FMA2(acc0, q2.y, r0[5]); FMA2(acc1, q2.y, r1[5]);
            FMA2(acc0, q3.x, r0[6]); FMA2(acc1, q3.x, r1[6]);
            FMA2(acc0, q3.y, r0[7]); FMA2(acc1, q3.y, r1[7]);

            float a0 = __uint_as_float((unsigned int)acc0);
            float a1 = __uint_as_float((unsigned int)(acc0 >> 32));
            float a2 = __uint_as_float((unsigned int)acc1);
            float a3 = __uint_as_float((unsigned int)(acc1 >> 32));

            float* outp = base_out + (size_t)d * DIM;
            asm volatile("red.global.add.v4.f32 [%0], {%1, %2, %3, %4};"
                         :: "l"(outp), "f"(a0), "f"(a1), "f"(a2), "f"(a3)
                         : "memory");
        }
    }
}

// ---------------------------------------------------------------------------
// 5) attention pooling (finalize fused into the gather)
// ---------------------------------------------------------------------------
__global__ void attn_kernel(const int* __restrict__ seed_ids,
                            const float* __restrict__ A,
                            const float* __restrict__ bvec,
                            const float* __restrict__ root,
                            const float* __restrict__ rbias) {
    __shared__ float H[SEED_LEN][DIM + 1];
    __shared__ float e_s[SEED_LEN];
    __shared__ float attnw[SEED_LEN];

    int b = blockIdx.x;
    int tid = threadIdx.x;
    int lane = tid & 31, warp = tid >> 5;

    for (int r = 0; r < SEED_LEN * DIM / 256; r++) {
        int idx = r * 256 + tid;
        int s = idx >> 7, d = idx & 127;
        int node = seed_ids[b * SEED_LEN + s];
        float invd = 1.0f / fmaxf(g_deg[node], 1.0f);
        H[s][d] = g_agg[(size_t)node * DIM + d] * invd +
                  __ldg(root + (size_t)node * DIM + d) + __ldg(rbias + d);
    }
    __syncthreads();

    float4 acc[4];
#pragma unroll
    for (int ss = 0; ss < 4; ss++) acc[ss] = make_float4(0.f, 0.f, 0.f, 0.f);
    int s0 = warp * 4;
#pragma unroll 4
    for (int k = 0; k < DIM; k++) {
        float4 a4 = __ldg((const float4*)(A + (size_t)k * DIM) + lane);
        float h0 = H[s0 + 0][k];
        float h1 = H[s0 + 1][k];
        float h2 = H[s0 + 2][k];
        float h3 = H[s0 + 3][k];
        acc[0].x = fmaf(h0, a4.x, acc[0].x); acc[0].y = fmaf(h0, a4.y, acc[0].y);
        acc[0].z = fmaf(h0, a4.z, acc[0].z); acc[0].w = fmaf(h0, a4.w, acc[0].w);
        acc[1].x = fmaf(h1, a4.x, acc[1].x); acc[1].y = fmaf(h1, a4.y, acc[1].y);
        acc[1].z = fmaf(h1, a4.z, acc[1].z); acc[1].w = fmaf(h1, a4.w, acc[1].w);
        acc[2].x = fmaf(h2, a4.x, acc[2].x); acc[2].y = fmaf(h2, a4.y, acc[2].y);
        acc[2].z = fmaf(h2, a4.z, acc[2].z); acc[2].w = fmaf(h2, a4.w, acc[2].w);
        acc[3].x = fmaf(h3, a4.x, acc[3].x); acc[3].y = fmaf(h3, a4.y, acc[3].y);
        acc[3].z = fmaf(h3, a4.z, acc[3].z); acc[3].w = fmaf(h3, a4.w, acc[3].w);
    }

    float4 b4 = __ldg((const float4*)bvec + lane);
#pragma unroll
    for (int ss = 0; ss < 4; ss++) {
        float v = tanhf(acc[ss].x) * b4.x + tanhf(acc[ss].y) * b4.y +
                  tanhf(acc[ss].z) * b4.z + tanhf(acc[ss].w) * b4.w;
#pragma unroll
        for (int o = 16; o > 0; o >>= 1) v += __shfl_xor_sync(0xffffffffu, v, o);
        if (lane == 0) e_s[s0 + ss] = v;
    }
    __syncthreads();

    if (warp == 0) {
        float ev = e_s[lane];
        float m = ev;
#pragma unroll
        for (int o = 16; o > 0; o >>= 1)
            m = fmaxf(m, __shfl_xor_sync(0xffffffffu, m, o));
        float ex = expf(ev - m);
        float ss2 = ex;
#pragma unroll
        for (int o = 16; o > 0; o >>= 1) ss2 += __shfl_xor_sync(0xffffffffu, ss2, o);
        attnw[lane] = ex / ss2;
    }
    __syncthreads();

    if (tid < DIM) {
        float u = 0.f;
#pragma unroll
        for (int s = 0; s < SEED_LEN; s++) u = fmaf(attnw[s], H[s][tid], u);
        g_u[b * DIM + tid] = u;
    }
}

// ---------------------------------------------------------------------------
// 6) scores: k-paired FFMA2. Row-major smem (consecutive-k pairs are already
//    contiguous -> LDS.128 = 2 u64 pairs). acc[i][j] is a u64 holding
//    (even-k sum, odd-k sum); epilogue adds lo+hi. Loader/stores = R15.
//    Per 4k per thread: 8 LDS.128 + 32 FFMA2 (was 32 LDS + 64 FFMA).
// ---------------------------------------------------------------------------
#define ETILE 64
#define KCH 64
#define KPAD 68   // row stride in floats: 272B, 16B-aligned for every row
__global__ void __launch_bounds__(256)
scores_kernel(const float* __restrict__ out_bias,
              const float* __restrict__ root,
              const float* __restrict__ rbias,
              float* __restrict__ out) {
    __shared__ __align__(16) float nS[ETILE][KPAD];
    __shared__ __align__(16) float uS[BATCH][KPAD];
    __shared__ float invd_s[ETILE];
    int e0 = blockIdx.x * ETILE;
    int tid = threadIdx.x;
    int ti = tid & 15;   // entities ti, ti+16, ti+32, ti+48
    int tj = tid >> 4;   // batches  tj, tj+16, tj+32, tj+48

    if (tid < ETILE) {
        int e = e0 + tid;
        invd_s[tid] = (e < N_ENTITY) ? 1.0f / fmaxf(g_deg[e], 1.0f) : 0.f;
    }

    unsigned long long acc[4][4];   // (even-k sum, odd-k sum) packed
#pragma unroll
    for (int i = 0; i < 4; i++)
#pragma unroll
        for (int j = 0; j < 4; j++) acc[i][j] = 0ull;

    for (int kc = 0; kc < DIM; kc += KCH) {
        __syncthreads();
        for (int q = tid; q < ETILE * (KCH / 4); q += 256) {
            int r = q >> 4;
            int c4 = (q & 15) * 4;
            int e = e0 + r;
            float4 nv = make_float4(0.f, 0.f, 0.f, 0.f);
            if (e < N_ENTITY) {
                float4 a = *(const float4*)(g_agg + (size_t)e * DIM + kc + c4);
                float4 rt = __ldg((const float4*)(root + (size_t)e * DIM + kc + c4));
                float4 bb = __ldg((const float4*)(rbias + kc + c4));
                float iv = invd_s[r];
                nv.x = a.x * iv + rt.x + bb.x;
                nv.y = a.y * iv + rt.y + bb.y;
                nv.z = a.z * iv + rt.z + bb.z;
                nv.w = a.w * iv + rt.w + bb.w;
            }
            *(float4*)&nS[r][c4] = nv;
            *(float4*)&uS[r][c4] = *(const float4*)(g_u + r * DIM + kc + c4);
        }
        __syncthreads();
#pragma unroll 4
        for (int k = 0; k < KCH; k += 4) {
            ulonglong2 nf[4], uf[4];
#pragma unroll
            for (int i = 0; i < 4; i++)
                nf[i] = *(const ulonglong2*)&nS[ti + 16 * i][k];
#pragma unroll
            for (int j = 0; j < 4; j++)
                uf[j] = *(const ulonglong2*)&uS[tj + 16 * j][k];
#pragma unroll
            for (int i = 0; i < 4; i++)
#pragma unroll
                for (int j = 0; j < 4; j++) {
                    FMA2(acc[i][j], nf[i].x, uf[j].x);
                    FMA2(acc[i][j], nf[i].y, uf[j].y);
                }
        }
    }

#pragma unroll
    for (int i = 0; i < 4; i++) {
        int e = e0 + ti + 16 * i;
        if (e >= N_ENTITY) continue;
        float ob = out_bias[e];
#pragma unroll
        for (int j = 0; j < 4; j++) {
            int bb = tj + 16 * j;
            float v = __uint_as_float((unsigned int)acc[i][j]) +
                      __uint_as_float((unsigned int)(acc[i][j] >> 32));
            out[(size_t)bb * N_ENTITY + e] = v + ob;
        }
    }
}

// ---------------------------------------------------------------------------
extern "C" void kernel_launch(void* const* d_in, const int* in_sizes, int n_in,
                              void* d_out, int out_size) {
    const int*   seed_ids = (const int*)d_in[0];
    const int*   edge_src = (const int*)d_in[1];
    const int*   edge_dst = (const int*)d_in[2];
    const int*   edge_typ = (const int*)d_in[3];
    const float* basis    = (const float*)d_in[4];
    const float* att      = (const float*)d_in[5];
    const float* root     = (const float*)d_in[6];
    const float* rbias    = (const float*)d_in[7];
    const float* attn_a   = (const float*)d_in[8];
    const float* attn_b   = (const float*)d_in[9];
    const float* out_bias = (const float*)d_in[10];
    float* out = (float*)d_out;

    hist_kernel<<<(N_EDGES + 255) / 256, 256>>>(edge_src);                        // 1
    scan_kernel<<<SCAN_NBLK, SCAN_BLK>>>();                                       // 2
    scatter_kernel<<<(N_EDGES + 255) / 256, 256>>>(edge_src, edge_dst, edge_typ); // 3
    agg_kernel<<<(N_ENTITY * 32 + 255) / 256, 256>>>(basis, att);                 // 4 (ncu)
    attn_kernel<<<BATCH, 256>>>(seed_ids, attn_a, attn_b, root, rbias);           // 5
    scores_kernel<<<(N_ENTITY + ETILE - 1) / ETILE, 256>>>(out_bias, root, rbias, out); // 6
}